// round 10
// baseline (speedup 1.0000x reference)
#include <cuda_runtime.h>
#include <cuda_fp16.h>
#include <cstdint>
#include <math.h>

#define NN 100000
#define EE 1600000
#define ET 1700000      // edges + self loops
#define H 14
#define C 7
#define HC 98
#define CP 8            // padded channels (slot 7 carries alsrc fp16)
#define HCP 112         // H * CP
#define FIN 256
#define CAP 64          // bucket capacity per node (P(deg>63) ~ 1e-16)

// ---------------- scratch (device globals; reused across both layers) ----------
__device__ __align__(16) __half g_xh[NN * HCP]; // [N,H,8] fp16; ch7 = alsrc
__device__ float g_aldst[NN * H];    // per-node dst logits
__device__ float g_h[NN * C];        // layer-1 output features
__device__ int g_cnt[NN];            // in-degree (filled by scatter)
__device__ __align__(16) int g_bucket[NN * CAP]; // per-destination source lists

__device__ __forceinline__ float lrelu(float v) {
    return v > 0.0f ? v : 0.2f * v;
}

__device__ __forceinline__ unsigned int f2tf(float f) {
    unsigned int r;
    asm("cvt.rna.tf32.f32 %0, %1;" : "=r"(r) : "f"(f));
    return r;
}

__device__ __forceinline__ void mma_tf32(float* c, const unsigned int* a,
                                         unsigned int b0, unsigned int b1) {
    asm volatile(
        "mma.sync.aligned.m16n8k8.row.col.f32.tf32.tf32.f32 "
        "{%0,%1,%2,%3},{%4,%5,%6,%7},{%8,%9},{%0,%1,%2,%3};"
        : "+f"(c[0]), "+f"(c[1]), "+f"(c[2]), "+f"(c[3])
        : "r"(a[0]), "r"(a[1]), "r"(a[2]), "r"(a[3]), "r"(b0), "r"(b1));
}

// ---------------- bucket CSR build ---------------------------------------------
__global__ void k_zero() {
    const int i = blockIdx.x * blockDim.x + threadIdx.x;
    if (i < NN) g_cnt[i] = 0;
}

__global__ void k_scatter(const int* __restrict__ ei) {
    const int e = blockIdx.x * blockDim.x + threadIdx.x;
    if (e >= ET) return;
    int s, d;
    if (e < EE) { s = ei[e]; d = ei[EE + e]; } else { s = d = e - EE; }
    const int pos = atomicAdd(&g_cnt[d], 1);
    g_bucket[(d << 6) + pos] = s;
}

// ---------------- GEMM1 (TF32 MMA) + fused attention logits --------------------
// x[N,256] @ W1[256,98] -> g_xh fp16 (alsrc packed in pad slot), g_aldst fp32
__global__ __launch_bounds__(256) void k_gemm1(const float* __restrict__ x,
                                               const float* __restrict__ W,
                                               const float* __restrict__ a_src,
                                               const float* __restrict__ a_dst) {
    __shared__ float As[128][20];
    __shared__ float Bs[16][120];
    __shared__ float a_s[HC], a_d[HC];
    const int tid = threadIdx.x;
    const int warp = tid >> 5, lane = tid & 31;
    const int gid = lane >> 2, t4 = lane & 3;
    const int wm = warp >> 1, wn = warp & 1;
    const int bm = blockIdx.x * 128;
    const int rb0 = wm * 32;
    const int cb  = wn * 56;

    if (tid < HC) { a_s[tid] = a_src[tid]; a_d[tid] = a_dst[tid]; }

    float acc[2][7][4];
#pragma unroll
    for (int mt = 0; mt < 2; mt++)
#pragma unroll
        for (int nt = 0; nt < 7; nt++)
#pragma unroll
            for (int q = 0; q < 4; q++) acc[mt][nt][q] = 0.0f;

    for (int k0 = 0; k0 < FIN; k0 += 16) {
#pragma unroll
        for (int i = 0; i < 2; i++) {
            const int idx = tid * 2 + i;
            const int row = idx >> 2, kq = idx & 3;
            float4 v = make_float4(0.f, 0.f, 0.f, 0.f);
            if (bm + row < NN) v = *(const float4*)&x[(size_t)(bm + row) * FIN + k0 + kq * 4];
            As[row][kq * 4 + 0] = v.x;
            As[row][kq * 4 + 1] = v.y;
            As[row][kq * 4 + 2] = v.z;
            As[row][kq * 4 + 3] = v.w;
        }
#pragma unroll
        for (int i = tid; i < 16 * HCP; i += 256) {
            const int k = i / HCP, cp = i % HCP;
            const int h = cp >> 3, c = cp & 7;
            Bs[k][cp] = (c < C) ? W[(size_t)(k0 + k) * HC + h * C + c] : 0.0f;
        }
        __syncthreads();
#pragma unroll
        for (int kk = 0; kk < 16; kk += 8) {
            unsigned int a[2][4];
#pragma unroll
            for (int mt = 0; mt < 2; mt++) {
                const int r = rb0 + mt * 16 + gid;
                a[mt][0] = f2tf(As[r][kk + t4]);
                a[mt][1] = f2tf(As[r + 8][kk + t4]);
                a[mt][2] = f2tf(As[r][kk + t4 + 4]);
                a[mt][3] = f2tf(As[r + 8][kk + t4 + 4]);
            }
#pragma unroll
            for (int nt = 0; nt < 7; nt++) {
                const unsigned int b0 = f2tf(Bs[kk + t4][cb + nt * 8 + gid]);
                const unsigned int b1 = f2tf(Bs[kk + t4 + 4][cb + nt * 8 + gid]);
#pragma unroll
                for (int mt = 0; mt < 2; mt++) mma_tf32(acc[mt][nt], a[mt], b0, b1);
            }
        }
        __syncthreads();
    }

    // epilogue: per fragment (rows r0, r0+8) x head nt -> logits + packed store
#pragma unroll
    for (int mt = 0; mt < 2; mt++) {
        const int r0 = bm + rb0 + mt * 16 + gid;
        const int r1 = r0 + 8;
#pragma unroll
        for (int nt = 0; nt < 7; nt++) {
            const int head = wn * 7 + nt;
            const int c0 = t4 * 2;
            const float as0 = a_s[head * C + c0];
            const float ad0 = a_d[head * C + c0];
            const float as1 = (t4 < 3) ? a_s[head * C + c0 + 1] : 0.0f;
            const float ad1 = (t4 < 3) ? a_d[head * C + c0 + 1] : 0.0f;
            float ps0 = acc[mt][nt][0] * as0 + acc[mt][nt][1] * as1;
            float pd0 = acc[mt][nt][0] * ad0 + acc[mt][nt][1] * ad1;
            float ps1 = acc[mt][nt][2] * as0 + acc[mt][nt][3] * as1;
            float pd1 = acc[mt][nt][2] * ad0 + acc[mt][nt][3] * ad1;
            // reduce over the 4 t4-lanes (adjacent lanes share gid)
            ps0 += __shfl_xor_sync(0xffffffffu, ps0, 1);
            ps0 += __shfl_xor_sync(0xffffffffu, ps0, 2);
            pd0 += __shfl_xor_sync(0xffffffffu, pd0, 1);
            pd0 += __shfl_xor_sync(0xffffffffu, pd0, 2);
            ps1 += __shfl_xor_sync(0xffffffffu, ps1, 1);
            ps1 += __shfl_xor_sync(0xffffffffu, ps1, 2);
            pd1 += __shfl_xor_sync(0xffffffffu, pd1, 1);
            pd1 += __shfl_xor_sync(0xffffffffu, pd1, 2);

            const int col = cb + nt * 8 + t4 * 2;
            if (r0 < NN) {
                const __half2 hv = (t4 == 3)
                    ? __floats2half2_rn(acc[mt][nt][0], ps0)   // (ch6, alsrc)
                    : __floats2half2_rn(acc[mt][nt][0], acc[mt][nt][1]);
                *(__half2*)&g_xh[(size_t)r0 * HCP + col] = hv;
                if (t4 == 0) g_aldst[r0 * H + head] = pd0;
            }
            if (r1 < NN) {
                const __half2 hv = (t4 == 3)
                    ? __floats2half2_rn(acc[mt][nt][2], ps1)
                    : __floats2half2_rn(acc[mt][nt][2], acc[mt][nt][3]);
                *(__half2*)&g_xh[(size_t)r1 * HCP + col] = hv;
                if (t4 == 0) g_aldst[r1 * H + head] = pd1;
            }
        }
    }
}

// ---------------- fused node pass: softmax + max agg + head reduce -------------
// 32 nodes/block, 14 threads/node (one per head); chunk-of-4 batched loads.
// alsrc arrives packed in channel 7 of each xh row -> single 16B load per edge.
template<int MODE>
__global__ __launch_bounds__(448) void k_node(const float* __restrict__ b,
                                              float* __restrict__ out) {
    __shared__ float sm[32][H][CP];          // 14 KB
    const int tid = threadIdx.x;             // 448 = 32 nodes * 14 heads
    const int ln = tid / H;
    const int h  = tid % H;
    const int n  = blockIdx.x * 32 + ln;

    if (n < NN) {
        const int cnt = g_cnt[n];
        const int base = n << 6;
        const float ad = g_aldst[n * H + h];
        float den = 0.0f;
        float a0 = -INFINITY, a1 = -INFINITY, a2 = -INFINITY, a3 = -INFINITY;
        float a4 = -INFINITY, a5 = -INFINITY, a6 = -INFINITY;

        for (int j0 = 0; j0 < cnt; j0 += 4) {
            const int4 q = *(const int4*)&g_bucket[base + j0];
            const int m = cnt - j0;
            int ss[4] = {q.x, q.y, q.z, q.w};
            uint4 u[4];
#pragma unroll
            for (int k = 0; k < 4; k++)
                if (k < m) u[k] = *(const uint4*)&g_xh[(size_t)ss[k] * HCP + h * CP];
#pragma unroll
            for (int k = 0; k < 4; k++) {
                if (k < m) {
                    const __half2* hp = (const __half2*)&u[k];
                    const float2 f0 = __half22float2(hp[0]);
                    const float2 f1 = __half22float2(hp[1]);
                    const float2 f2 = __half22float2(hp[2]);
                    const float2 f3 = __half22float2(hp[3]);  // (ch6, alsrc)
                    const float l = lrelu(f3.y + ad);
                    const float w = __expf(l);
                    den += w;
                    a0 = fmaxf(a0, w * f0.x);
                    a1 = fmaxf(a1, w * f0.y);
                    a2 = fmaxf(a2, w * f1.x);
                    a3 = fmaxf(a3, w * f1.y);
                    a4 = fmaxf(a4, w * f2.x);
                    a5 = fmaxf(a5, w * f2.y);
                    a6 = fmaxf(a6, w * f3.x);
                }
            }
        }
        const float inv = 1.0f / den;        // den > 0 (self loop => deg >= 1)
        sm[ln][h][0] = a0 * inv;
        sm[ln][h][1] = a1 * inv;
        sm[ln][h][2] = a2 * inv;
        sm[ln][h][3] = a3 * inv;
        sm[ln][h][4] = a4 * inv;
        sm[ln][h][5] = a5 * inv;
        sm[ln][h][6] = a6 * inv;
    }
    __syncthreads();

    if (MODE == 0) {
        if (tid < 32 * C) {
            const int l2 = tid / C, c = tid % C;
            const int nn = blockIdx.x * 32 + l2;
            if (nn < NN) {
                float s = 0.0f;
#pragma unroll
                for (int hh = 0; hh < H; hh++) s += sm[l2][hh][c];
                out[nn * C + c] = fmaxf(s * (1.0f / H) + b[c], 0.0f);
            }
        }
    } else {
        if (tid < 32) {
            const int nn = blockIdx.x * 32 + tid;
            if (nn < NN) {
                float v[C];
#pragma unroll
                for (int c = 0; c < C; c++) {
                    float s = 0.0f;
#pragma unroll
                    for (int hh = 0; hh < H; hh++) s += sm[tid][hh][c];
                    v[c] = s * (1.0f / H) + b[c];
                }
                float mx = v[0];
#pragma unroll
                for (int c = 1; c < C; c++) mx = fmaxf(mx, v[c]);
                float se = 0.0f;
#pragma unroll
                for (int c = 0; c < C; c++) se += __expf(v[c] - mx);
                const float lse = mx + logf(se);
#pragma unroll
                for (int c = 0; c < C; c++) out[nn * C + c] = v[c] - lse;
            }
        }
    }
}

// ---------------- fused GEMM2 + attention logits (layer 2) ---------------------
__global__ __launch_bounds__(256) void k_gemm2al(const float* __restrict__ W2,
                                                 const float* __restrict__ a_src,
                                                 const float* __restrict__ a_dst) {
    __shared__ float W2s[C][HC];   // 7 x 98
    __shared__ float As[HC], Ad[HC];
    const int tid = threadIdx.x;
    for (int i = tid; i < C * HC; i += 256) W2s[i / HC][i % HC] = W2[i];
    for (int i = tid; i < HC; i += 256) { As[i] = a_src[i]; Ad[i] = a_dst[i]; }
    __syncthreads();

    const int i = blockIdx.x * 256 + tid;
    if (i >= NN * H) return;
    const int n = i / H, h = i % H;
    float hv[C];
#pragma unroll
    for (int k = 0; k < C; k++) hv[k] = g_h[n * C + k];
    float o[C];
    float s1 = 0.0f, s2 = 0.0f;
#pragma unroll
    for (int c = 0; c < C; c++) {
        float s = 0.0f;
#pragma unroll
        for (int k = 0; k < C; k++) s = fmaf(hv[k], W2s[k][h * C + c], s);
        o[c] = s;
        s1 = fmaf(s, As[h * C + c], s1);
        s2 = fmaf(s, Ad[h * C + c], s2);
    }
    g_aldst[i] = s2;
    uint4 u;
    __half2* hp = (__half2*)&u;
    hp[0] = __floats2half2_rn(o[0], o[1]);
    hp[1] = __floats2half2_rn(o[2], o[3]);
    hp[2] = __floats2half2_rn(o[4], o[5]);
    hp[3] = __floats2half2_rn(o[6], s1);   // pack alsrc into pad slot
    *(uint4*)&g_xh[(size_t)n * HCP + h * CP] = u;
}

extern "C" void kernel_launch(void* const* d_in, const int* in_sizes, int n_in,
                              void* d_out, int out_size) {
    const float* x      = (const float*)d_in[0];
    const int*   ei     = (const int*)  d_in[1];
    const float* W1     = (const float*)d_in[2];
    const float* a_src1 = (const float*)d_in[3];
    const float* a_dst1 = (const float*)d_in[4];
    const float* b1     = (const float*)d_in[5];
    const float* W2     = (const float*)d_in[6];
    const float* a_src2 = (const float*)d_in[7];
    const float* a_dst2 = (const float*)d_in[8];
    const float* b2     = (const float*)d_in[9];
    float* out = (float*)d_out;

    const int EB = (ET + 255) / 256;
    const int NB = (NN + 31) / 32;

    float* g_h_ptr;
    cudaGetSymbolAddress((void**)&g_h_ptr, g_h);

    // ----- bucket CSR (shared by both layers) -----
    k_zero   <<<(NN + 255) / 256, 256>>>();
    k_scatter<<<EB, 256>>>(ei);

    // ----- layer 1 -----
    k_gemm1  <<<(NN + 127) / 128, 256>>>(x, W1, a_src1, a_dst1);
    k_node<0><<<NB, 448>>>(b1, g_h_ptr);

    // ----- layer 2 -----
    k_gemm2al<<<(NN * H + 255) / 256, 256>>>(W2, a_src2, a_dst2);
    k_node<1><<<NB, 448>>>(b2, out);
}

// round 11
// speedup vs baseline: 1.6269x; 1.6269x over previous
#include <cuda_runtime.h>
#include <cuda_fp16.h>
#include <cstdint>
#include <math.h>

#define NN 100000
#define EE 1600000
#define ET 1700000      // edges + self loops
#define H 14
#define C 7
#define HC 98
#define CP 8            // padded channels (slot 7 carries alsrc fp16)
#define HCP 112         // H * CP
#define FIN 256
#define CAP 64          // bucket capacity per node (P(deg>63) ~ 1e-16)

// ---------------- scratch (device globals; reused across both layers) ----------
__device__ __align__(16) __half g_xh[NN * HCP]; // [N,H,8] fp16; ch7 = alsrc
__device__ float g_aldst[NN * H];    // per-node dst logits
__device__ float g_h[NN * C];        // layer-1 output features
__device__ int g_cnt[NN];            // in-degree (filled by scatter)
__device__ __align__(16) int g_bucket[NN * CAP]; // per-destination source lists

__device__ __forceinline__ float lrelu(float v) {
    return v > 0.0f ? v : 0.2f * v;
}

__device__ __forceinline__ unsigned int f2tf(float f) {
    unsigned int r;
    asm("cvt.rna.tf32.f32 %0, %1;" : "=r"(r) : "f"(f));
    return r;
}

__device__ __forceinline__ void mma_tf32(float* c, const unsigned int* a,
                                         unsigned int b0, unsigned int b1) {
    asm volatile(
        "mma.sync.aligned.m16n8k8.row.col.f32.tf32.tf32.f32 "
        "{%0,%1,%2,%3},{%4,%5,%6,%7},{%8,%9},{%0,%1,%2,%3};"
        : "+f"(c[0]), "+f"(c[1]), "+f"(c[2]), "+f"(c[3])
        : "r"(a[0]), "r"(a[1]), "r"(a[2]), "r"(a[3]), "r"(b0), "r"(b1));
}

// ---------------- bucket CSR build ---------------------------------------------
__global__ void k_zero() {
    const int i = blockIdx.x * blockDim.x + threadIdx.x;
    if (i < NN) g_cnt[i] = 0;
}

__global__ void k_scatter(const int* __restrict__ ei) {
    const int e = blockIdx.x * blockDim.x + threadIdx.x;
    if (e >= ET) return;
    int s, d;
    if (e < EE) { s = ei[e]; d = ei[EE + e]; } else { s = d = e - EE; }
    const int pos = atomicAdd(&g_cnt[d], 1);
    g_bucket[(d << 6) + pos] = s;
}

// ---------------- GEMM1 (TF32 MMA): x[N,256] @ W1[256,98] -> g_xh fp16 ---------
__global__ __launch_bounds__(256) void k_gemm1(const float* __restrict__ x,
                                               const float* __restrict__ W) {
    __shared__ float As[128][20];
    __shared__ float Bs[16][120];
    const int tid = threadIdx.x;
    const int warp = tid >> 5, lane = tid & 31;
    const int gid = lane >> 2, t4 = lane & 3;
    const int wm = warp >> 1, wn = warp & 1;
    const int bm = blockIdx.x * 128;
    const int rb0 = wm * 32;
    const int cb  = wn * 56;

    float acc[2][7][4];
#pragma unroll
    for (int mt = 0; mt < 2; mt++)
#pragma unroll
        for (int nt = 0; nt < 7; nt++)
#pragma unroll
            for (int q = 0; q < 4; q++) acc[mt][nt][q] = 0.0f;

    for (int k0 = 0; k0 < FIN; k0 += 16) {
#pragma unroll
        for (int i = 0; i < 2; i++) {
            const int idx = tid * 2 + i;
            const int row = idx >> 2, kq = idx & 3;
            float4 v = make_float4(0.f, 0.f, 0.f, 0.f);
            if (bm + row < NN) v = *(const float4*)&x[(size_t)(bm + row) * FIN + k0 + kq * 4];
            As[row][kq * 4 + 0] = v.x;
            As[row][kq * 4 + 1] = v.y;
            As[row][kq * 4 + 2] = v.z;
            As[row][kq * 4 + 3] = v.w;
        }
#pragma unroll
        for (int i = tid; i < 16 * HCP; i += 256) {
            const int k = i / HCP, cp = i % HCP;
            const int h = cp >> 3, c = cp & 7;
            Bs[k][cp] = (c < C) ? W[(size_t)(k0 + k) * HC + h * C + c] : 0.0f;
        }
        __syncthreads();
#pragma unroll
        for (int kk = 0; kk < 16; kk += 8) {
            unsigned int a[2][4];
#pragma unroll
            for (int mt = 0; mt < 2; mt++) {
                const int r = rb0 + mt * 16 + gid;
                a[mt][0] = f2tf(As[r][kk + t4]);
                a[mt][1] = f2tf(As[r + 8][kk + t4]);
                a[mt][2] = f2tf(As[r][kk + t4 + 4]);
                a[mt][3] = f2tf(As[r + 8][kk + t4 + 4]);
            }
#pragma unroll
            for (int nt = 0; nt < 7; nt++) {
                const unsigned int b0 = f2tf(Bs[kk + t4][cb + nt * 8 + gid]);
                const unsigned int b1 = f2tf(Bs[kk + t4 + 4][cb + nt * 8 + gid]);
#pragma unroll
                for (int mt = 0; mt < 2; mt++) mma_tf32(acc[mt][nt], a[mt], b0, b1);
            }
        }
        __syncthreads();
    }
#pragma unroll
    for (int mt = 0; mt < 2; mt++) {
        const int r0 = bm + rb0 + mt * 16 + gid;
#pragma unroll
        for (int nt = 0; nt < 7; nt++) {
            const int col = cb + nt * 8 + t4 * 2;
            if (r0 < NN)
                *(__half2*)&g_xh[(size_t)r0 * HCP + col] =
                    __floats2half2_rn(acc[mt][nt][0], acc[mt][nt][1]);
            if (r0 + 8 < NN)
                *(__half2*)&g_xh[(size_t)(r0 + 8) * HCP + col] =
                    __floats2half2_rn(acc[mt][nt][2], acc[mt][nt][3]);
        }
    }
}

// ---------------- attention logits: pack alsrc into xh pad slot ----------------
__global__ void k_al(const float* __restrict__ a_src, const float* __restrict__ a_dst) {
    const int i = blockIdx.x * blockDim.x + threadIdx.x;
    if (i >= NN * H) return;
    const int n = i / H, h = i % H;
    const uint4 u = *(const uint4*)&g_xh[(size_t)n * HCP + h * CP];
    const __half2* hp = (const __half2*)&u;
    float xv[8];
    float2 f;
    f = __half22float2(hp[0]); xv[0] = f.x; xv[1] = f.y;
    f = __half22float2(hp[1]); xv[2] = f.x; xv[3] = f.y;
    f = __half22float2(hp[2]); xv[4] = f.x; xv[5] = f.y;
    f = __half22float2(hp[3]); xv[6] = f.x;
    float s1 = 0.0f, s2 = 0.0f;
#pragma unroll
    for (int c = 0; c < C; c++) {
        s1 = fmaf(xv[c], a_src[h * C + c], s1);
        s2 = fmaf(xv[c], a_dst[h * C + c], s2);
    }
    g_aldst[i] = s2;
    g_xh[(size_t)n * HCP + h * CP + 7] = __float2half_rn(s1);  // pack alsrc
}

// ---------------- fused node pass: softmax + max agg + head reduce -------------
// 32 nodes/block, 14 threads/node; fp16x2 inner math; alsrc packed in ch7.
template<int MODE>
__global__ __launch_bounds__(448, 3) void k_node(const float* __restrict__ b,
                                                 float* __restrict__ out) {
    __shared__ float sm[32][H][CP];          // 14 KB
    const int tid = threadIdx.x;             // 448 = 32 nodes * 14 heads
    const int ln = tid / H;
    const int h  = tid % H;
    const int n  = blockIdx.x * 32 + ln;

    if (n < NN) {
        const int cnt = g_cnt[n];
        const int base = n << 6;
        const float ad = g_aldst[n * H + h];
        float den = 0.0f;
        const __half2 NEG2 = __float2half2_rn(-INFINITY);
        __half2 ah0 = NEG2, ah1 = NEG2, ah2 = NEG2, ah3 = NEG2;

        for (int j0 = 0; j0 < cnt; j0 += 4) {
            const int4 q = *(const int4*)&g_bucket[base + j0];
            const int m = cnt - j0;
            int ss[4] = {q.x, q.y, q.z, q.w};
            uint4 u[4];
#pragma unroll
            for (int k = 0; k < 4; k++)
                if (k < m) u[k] = *(const uint4*)&g_xh[(size_t)ss[k] * HCP + h * CP];
#pragma unroll
            for (int k = 0; k < 4; k++) {
                if (k < m) {
                    const __half2* hp = (const __half2*)&u[k];
                    const float als = __half2float(__high2half(hp[3]));
                    const float l = lrelu(als + ad);
                    const float w = __expf(l);
                    den += w;
                    const __half2 w2 = __float2half2_rn(w);
                    ah0 = __hmax2(ah0, __hmul2(w2, hp[0]));
                    ah1 = __hmax2(ah1, __hmul2(w2, hp[1]));
                    ah2 = __hmax2(ah2, __hmul2(w2, hp[2]));
                    ah3 = __hmax2(ah3, __hmul2(w2, hp[3]));  // .y garbage, discarded
                }
            }
        }
        const float inv = 1.0f / den;        // den > 0 (self loop => deg >= 1)
        const float2 F0 = __half22float2(ah0);
        const float2 F1 = __half22float2(ah1);
        const float2 F2 = __half22float2(ah2);
        const float2 F3 = __half22float2(ah3);
        sm[ln][h][0] = F0.x * inv;
        sm[ln][h][1] = F0.y * inv;
        sm[ln][h][2] = F1.x * inv;
        sm[ln][h][3] = F1.y * inv;
        sm[ln][h][4] = F2.x * inv;
        sm[ln][h][5] = F2.y * inv;
        sm[ln][h][6] = F3.x * inv;
    }
    __syncthreads();

    if (MODE == 0) {
        if (tid < 32 * C) {
            const int l2 = tid / C, c = tid % C;
            const int nn = blockIdx.x * 32 + l2;
            if (nn < NN) {
                float s = 0.0f;
#pragma unroll
                for (int hh = 0; hh < H; hh++) s += sm[l2][hh][c];
                out[nn * C + c] = fmaxf(s * (1.0f / H) + b[c], 0.0f);
            }
        }
    } else {
        if (tid < 32) {
            const int nn = blockIdx.x * 32 + tid;
            if (nn < NN) {
                float v[C];
#pragma unroll
                for (int c = 0; c < C; c++) {
                    float s = 0.0f;
#pragma unroll
                    for (int hh = 0; hh < H; hh++) s += sm[tid][hh][c];
                    v[c] = s * (1.0f / H) + b[c];
                }
                float mx = v[0];
#pragma unroll
                for (int c = 1; c < C; c++) mx = fmaxf(mx, v[c]);
                float se = 0.0f;
#pragma unroll
                for (int c = 0; c < C; c++) se += __expf(v[c] - mx);
                const float lse = mx + logf(se);
#pragma unroll
                for (int c = 0; c < C; c++) out[nn * C + c] = v[c] - lse;
            }
        }
    }
}

// ---------------- fused GEMM2 + attention logits (layer 2) ---------------------
__global__ __launch_bounds__(256) void k_gemm2al(const float* __restrict__ W2,
                                                 const float* __restrict__ a_src,
                                                 const float* __restrict__ a_dst) {
    __shared__ float W2s[C][HC];   // 7 x 98
    __shared__ float As[HC], Ad[HC];
    const int tid = threadIdx.x;
    for (int i = tid; i < C * HC; i += 256) W2s[i / HC][i % HC] = W2[i];
    for (int i = tid; i < HC; i += 256) { As[i] = a_src[i]; Ad[i] = a_dst[i]; }
    __syncthreads();

    const int i = blockIdx.x * 256 + tid;
    if (i >= NN * H) return;
    const int n = i / H, h = i % H;
    float hv[C];
#pragma unroll
    for (int k = 0; k < C; k++) hv[k] = g_h[n * C + k];
    float o[C];
    float s1 = 0.0f, s2 = 0.0f;
#pragma unroll
    for (int c = 0; c < C; c++) {
        float s = 0.0f;
#pragma unroll
        for (int k = 0; k < C; k++) s = fmaf(hv[k], W2s[k][h * C + c], s);
        o[c] = s;
        s1 = fmaf(s, As[h * C + c], s1);
        s2 = fmaf(s, Ad[h * C + c], s2);
    }
    g_aldst[i] = s2;
    uint4 u;
    __half2* hp = (__half2*)&u;
    hp[0] = __floats2half2_rn(o[0], o[1]);
    hp[1] = __floats2half2_rn(o[2], o[3]);
    hp[2] = __floats2half2_rn(o[4], o[5]);
    hp[3] = __floats2half2_rn(o[6], s1);   // pack alsrc into pad slot
    *(uint4*)&g_xh[(size_t)n * HCP + h * CP] = u;
}

extern "C" void kernel_launch(void* const* d_in, const int* in_sizes, int n_in,
                              void* d_out, int out_size) {
    const float* x      = (const float*)d_in[0];
    const int*   ei     = (const int*)  d_in[1];
    const float* W1     = (const float*)d_in[2];
    const float* a_src1 = (const float*)d_in[3];
    const float* a_dst1 = (const float*)d_in[4];
    const float* b1     = (const float*)d_in[5];
    const float* W2     = (const float*)d_in[6];
    const float* a_src2 = (const float*)d_in[7];
    const float* a_dst2 = (const float*)d_in[8];
    const float* b2     = (const float*)d_in[9];
    float* out = (float*)d_out;

    const int EB = (ET + 255) / 256;
    const int NB = (NN + 31) / 32;

    float* g_h_ptr;
    cudaGetSymbolAddress((void**)&g_h_ptr, g_h);

    // ----- bucket CSR (shared by both layers) -----
    k_zero   <<<(NN + 255) / 256, 256>>>();
    k_scatter<<<EB, 256>>>(ei);

    // ----- layer 1 -----
    k_gemm1  <<<(NN + 127) / 128, 256>>>(x, W1);
    k_al     <<<(NN * H + 255) / 256, 256>>>(a_src1, a_dst1);
    k_node<0><<<NB, 448>>>(b1, g_h_ptr);

    // ----- layer 2 -----
    k_gemm2al<<<(NN * H + 255) / 256, 256>>>(W2, a_src2, a_dst2);
    k_node<1><<<NB, 448>>>(b2, out);
}